// round 3
// baseline (speedup 1.0000x reference)
#include <cuda_runtime.h>
#include <cstdint>

// ---------------- problem constants ----------------
#define TOTAL_PIX (32*64*64)      // padded M = 131072
#define KTOT      2304            // 9 * 256
#define COUT      256
#define BM        128
#define BN        256
#define BK        32
#define NS        3               // pipeline stages
#define NITER     72              // KTOT / 32
#define SPARSE_TH 0.01f

// ---------------- smem layout (dynamic) ------------
#define SMEM_A_STRIDE 16384                    // 128 rows * 128B
#define SMEM_B_OFF    (3*16384)
#define SMEM_B_STRIDE 32768                    // 256 rows * 128B
#define SMEM_TOTAL    (SMEM_B_OFF + 3*SMEM_B_STRIDE)   // 147456 (144KB)

// ---------------- device scratch -------------------
__device__ __align__(16) float g_x [TOTAL_PIX * 256];   // tf32-rounded activations
__device__ __align__(16) float g_wt[COUT * KTOT];       // masked+rounded, [ko][k] K-major

// ---------------- helpers --------------------------
__device__ __forceinline__ uint32_t smem_u32(const void* p) {
    uint32_t a;
    asm("{ .reg .u64 t; cvta.to.shared.u64 t, %1; cvt.u32.u64 %0, t; }" : "=r"(a) : "l"(p));
    return a;
}
#define SWZ128(o) ((o) ^ (((o) >> 3) & 0x70))

__device__ __forceinline__ void cp_async16(uint32_t dst, const void* src, int sz) {
    asm volatile("cp.async.cg.shared.global [%0], [%1], 16, %2;"
                 :: "r"(dst), "l"(src), "r"(sz));
}
#define CP_COMMIT() asm volatile("cp.async.commit_group;" ::: "memory")
#define CP_WAIT(N)  asm volatile("cp.async.wait_group %0;" :: "n"(N) : "memory")

#define LDSM4(r0, r1, r2, r3, addr) \
    asm volatile("ldmatrix.sync.aligned.m8n8.x4.shared.b16 {%0,%1,%2,%3}, [%4];" \
        : "=r"(r0), "=r"(r1), "=r"(r2), "=r"(r3) : "r"(addr))

#define MMA_TF32(d, a, b) \
    asm volatile("mma.sync.aligned.m16n8k8.row.col.f32.tf32.tf32.f32 " \
        "{%0,%1,%2,%3}, {%4,%5,%6,%7}, {%8,%9}, {%0,%1,%2,%3};" \
        : "+f"((d)[0]), "+f"((d)[1]), "+f"((d)[2]), "+f"((d)[3]) \
        : "r"((a)[0]), "r"((a)[1]), "r"((a)[2]), "r"((a)[3]), \
          "r"((b)[0]), "r"((b)[1]))

__device__ __forceinline__ float rn_tf32(float v) {
    uint32_t o;
    asm("cvt.rna.tf32.f32 %0, %1;" : "=r"(o) : "f"(v));
    return __uint_as_float(o);
}

// ---------------- prep kernels ---------------------
// weight (256,256,3,3) OIHW -> g_wt[ko][ (r*3+s)*256 + ci ], masked + tf32-rounded
__global__ void prep_w(const float* __restrict__ w) {
    int i = blockIdx.x * blockDim.x + threadIdx.x;
    if (i >= COUT * KTOT) return;
    int ko = i / KTOT, k = i - ko * KTOT;
    int rs = k >> 8, ci = k & 255;
    float v = w[ko * KTOT + ci * 9 + rs];
    v = (fabsf(v) < SPARSE_TH) ? 0.0f : v;
    g_wt[i] = rn_tf32(v);
}

__global__ void prep_x(const float4* __restrict__ x) {
    const int N4 = TOTAL_PIX * 256 / 4;
    float4* gx4 = reinterpret_cast<float4*>(g_x);
    for (int i = blockIdx.x * blockDim.x + threadIdx.x; i < N4; i += gridDim.x * blockDim.x) {
        float4 v = x[i];
        v.x = rn_tf32(v.x); v.y = rn_tf32(v.y);
        v.z = rn_tf32(v.z); v.w = rn_tf32(v.w);
        gx4[i] = v;
    }
}

// ---------------- main conv kernel -----------------
__global__ void __launch_bounds__(256, 1)
conv_kernel(const float* __restrict__ bias, float* __restrict__ out) {
    extern __shared__ char smem[];
    uint32_t sb  = smem_u32(smem);
    int tid  = threadIdx.x;
    int warp = tid >> 5, lid = tid & 31;
    int mbase = blockIdx.x * BM;

    // warp tile position: 2 (m) x 4 (n) warps, each 64x64
    const int wm = (warp >> 2) * 64;
    const int wn = (warp & 3) * 64;
    // ldmatrix per-lane row/col components
    const uint32_t laneRA  = (((lid >> 3) & 1) << 3) + (lid & 7);
    const uint32_t laneK16A = (uint32_t)(lid >> 4) << 4;
    const uint32_t laneRB  = ((lid >> 4) << 3) + (lid & 7);
    const uint32_t laneK16B = (uint32_t)((lid >> 3) & 1) << 4;

    float acc[4][8][4];
    #pragma unroll
    for (int i = 0; i < 4; i++)
        #pragma unroll
        for (int j = 0; j < 8; j++)
            #pragma unroll
            for (int c = 0; c < 4; c++) acc[i][j][c] = 0.0f;

    // stage loader: stage `it` -> buffer it%NS
    auto load_stage = [&](int it) {
        int buf = it % NS;
        int rs  = it >> 3;                       // 3x3 tap index
        int ci0 = (it & 7) << 5;                 // input-channel chunk
        int d   = (rs / 3) * 64 + (rs % 3);      // linear pixel shift
        uint32_t abase = sb + buf * SMEM_A_STRIDE;
        uint32_t bbase = sb + SMEM_B_OFF + buf * SMEM_B_STRIDE;
        int k0 = it << 5;
        #pragma unroll
        for (int i = 0; i < 2; i++) {            // A tile: 128 rows x 32 fp32 (1024 x 16B)
            int j = tid + i * 256;
            int row = j >> 3, c = j & 7;
            int pix = mbase + d + row;
            uint32_t off = (uint32_t)(row * 128 + c * 16);
            int ok = (pix < TOTAL_PIX);
            const float* src = g_x + ((size_t)(ok ? pix : 0)) * 256 + ci0 + c * 4;
            cp_async16(abase + SWZ128(off), src, ok ? 16 : 0);
        }
        #pragma unroll
        for (int i = 2; i < 4; i++) {            // second half of A
            int j = tid + i * 256;
            int row = j >> 3, c = j & 7;
            int pix = mbase + d + row;
            uint32_t off = (uint32_t)(row * 128 + c * 16);
            int ok = (pix < TOTAL_PIX);
            const float* src = g_x + ((size_t)(ok ? pix : 0)) * 256 + ci0 + c * 4;
            cp_async16(abase + SWZ128(off), src, ok ? 16 : 0);
        }
        #pragma unroll
        for (int i = 0; i < 8; i++) {            // B tile: 256 rows(ko) x 32 fp32
            int j = tid + i * 256;
            int row = j >> 3, c = j & 7;
            uint32_t off = (uint32_t)(row * 128 + c * 16);
            const float* src = g_wt + (size_t)row * KTOT + k0 + c * 4;
            cp_async16(bbase + SWZ128(off), src, 16);
        }
        CP_COMMIT();
    };

    load_stage(0);
    load_stage(1);

    for (int it = 0; it < NITER; ++it) {
        int buf = it % NS;
        if (it == NITER - 1) { CP_WAIT(0); } else { CP_WAIT(1); }
        __syncthreads();

        if (it + 2 < NITER) load_stage(it + 2);  // fills buffer freed at last sync

        uint32_t abase = sb + buf * SMEM_A_STRIDE;
        uint32_t bbase = sb + SMEM_B_OFF + buf * SMEM_B_STRIDE;
        #pragma unroll
        for (int s = 0; s < 4; s++) {            // 4 x K=8 steps
            uint32_t a[4][4], b[8][2];
            #pragma unroll
            for (int i = 0; i < 4; i++) {
                uint32_t off = (uint32_t)((wm + i * 16 + laneRA) * 128) + s * 32 + laneK16A;
                LDSM4(a[i][0], a[i][1], a[i][2], a[i][3], abase + SWZ128(off));
            }
            #pragma unroll
            for (int jj = 0; jj < 4; jj++) {
                uint32_t off = (uint32_t)((wn + jj * 16 + laneRB) * 128) + s * 32 + laneK16B;
                LDSM4(b[2*jj][0], b[2*jj][1], b[2*jj+1][0], b[2*jj+1][1], bbase + SWZ128(off));
            }
            #pragma unroll
            for (int i = 0; i < 4; i++)
                #pragma unroll
                for (int j = 0; j < 8; j++)
                    MMA_TF32(acc[i][j], a[i], b[j]);
        }
    }

    // ---------------- epilogue ----------------
    int groupr = lid >> 2, tig = lid & 3;
    float2 bv[8];
    #pragma unroll
    for (int j = 0; j < 8; j++) {
        int col = wn + j * 8 + 2 * tig;
        bv[j].x = __ldg(&bias[col]);
        bv[j].y = __ldg(&bias[col + 1]);
    }
    #pragma unroll
    for (int i = 0; i < 4; i++) {
        #pragma unroll
        for (int h = 0; h < 2; h++) {
            int row = wm + i * 16 + groupr + h * 8;
            int mp  = mbase + row;
            int n = mp >> 12, p = (mp >> 6) & 63, q = mp & 63;
            if (p < 62 && q < 62) {
                float* op = out + (((size_t)((n * 62 + p) * 62 + q)) << 8) + wn + 2 * tig;
                #pragma unroll
                for (int j = 0; j < 8; j++) {
                    float2 v;
                    v.x = acc[i][j][h * 2 + 0] + bv[j].x;
                    v.y = acc[i][j][h * 2 + 1] + bv[j].y;
                    *reinterpret_cast<float2*>(op + j * 8) = v;
                }
            }
        }
    }
}

// ---------------- launch ---------------------------
extern "C" void kernel_launch(void* const* d_in, const int* in_sizes, int n_in,
                              void* d_out, int out_size) {
    (void)in_sizes; (void)n_in; (void)out_size;
    const float* x    = (const float*)d_in[0];
    const float* w    = (const float*)d_in[1];
    const float* bias = (const float*)d_in[2];
    float* out        = (float*)d_out;

    prep_w<<<(COUT * KTOT + 255) / 256, 256>>>(w);
    prep_x<<<8192, 256>>>((const float4*)x);

    cudaFuncSetAttribute(conv_kernel, cudaFuncAttributeMaxDynamicSharedMemorySize, SMEM_TOTAL);
    conv_kernel<<<TOTAL_PIX / BM, 256, SMEM_TOTAL>>>(bias, out);
}